// round 11
// baseline (speedup 1.0000x reference)
#include <cuda_runtime.h>
#include <cuda_bf16.h>

// TemporalConsistencyLoss — R11: algorithmic ordering (O(S log^2 S) D&C),
// pure-BCE stream, shared transitivity. Single launch (graph-safe).
//
//  ordering_sum_b = sum_{p<q in tt-sorted order} max(0, v_q - v_p + 0.5)
//                   + 0.5 * (S^2 - S(S-1)/2)          [v = pred_times in tt order]
//  Blocks 0..3   : per-batch ordering via bitonic sort + merge-D&C in smem.
//  Blocks 4..443 : BCE stream over 128 MB (2 LDG.128 + ~18 ops / 32 B).
//  All blocks    : transitivity over prec[0] (16 MB), then partial+ticket.

#define S_DIM 2048
#define B_DIM 4
#define SS (S_DIM * S_DIM)              // 2^22
#define NTOT (B_DIM * SS)               // 2^24
#define NTHR 512
#define NBLK 444                        // 148 SMs * 3 CTAs
#define NORD 4
#define NSTRM (NBLK - NORD)             // 440

__device__ double g_part[NBLK][3];
__device__ unsigned int g_ticket;       // zero at load; reset by last block

__global__ void __launch_bounds__(NTHR, 3) tcl_kernel(
    const float* __restrict__ pred_times,
    const float* __restrict__ pred_causal,
    const float* __restrict__ target_times,
    const int*   __restrict__ target_causal,
    const int*   __restrict__ target_prec,
    float* __restrict__ out, int out_size)
{
    __shared__ float sa[S_DIM];          // sort keys / prefix sums
    __shared__ float sb[S_DIM];          // payload / merge ping
    __shared__ float sc[S_DIM];          // merge pong
    __shared__ double sh0[NTHR], sh1[NTHR], sh2[NTHR];

    const int tid = threadIdx.x;
    const int bid = blockIdx.x;
    float ord = 0.0f, bce = 0.0f, tr = 0.0f;

    if (bid < NORD) {
        // ============ ORDERING for batch b = bid (exact, O(S log^2 S)) =====
        const float* __restrict__ ttrow = target_times + (bid << 11);
        const float* __restrict__ ptrow = pred_times + (bid << 11);
        for (int x = tid; x < S_DIM; x += NTHR) { sa[x] = ttrow[x]; sb[x] = ptrow[x]; }
        __syncthreads();

        // bitonic sort ascending by tt (sa), payload pt (sb)
        for (int k = 2; k <= S_DIM; k <<= 1) {
            for (int j = k >> 1; j > 0; j >>= 1) {
                for (int x = tid; x < S_DIM; x += NTHR) {
                    int ixj = x ^ j;
                    if (ixj > x) {
                        float ka = sa[x], kb = sa[ixj];
                        bool asc = ((x & k) == 0);
                        if ((ka > kb) == asc) {
                            sa[x] = kb; sa[ixj] = ka;
                            float pa = sb[x]; sb[x] = sb[ixj]; sb[ixj] = pa;
                        }
                    }
                }
                __syncthreads();
            }
        }

        // merge-D&C over v (pt in tt-order): cur starts in sb, ps in sa
        float* cur = sb;
        float* nxt = sc;
        float* ps  = sa;
        for (int m = 1; m <= S_DIM / 2; m <<= 1) {
            // segmented inclusive prefix sum of cur (segments of size m) -> ps
            for (int x = tid; x < S_DIM; x += NTHR) ps[x] = cur[x];
            __syncthreads();
            for (int d = 1; d < m; d <<= 1) {
                float t0 = (( tid          & (m - 1)) >= d) ? ps[tid          - d] : 0.0f;
                float t1 = (((tid + 512)   & (m - 1)) >= d) ? ps[tid + 512    - d] : 0.0f;
                float t2 = (((tid + 1024)  & (m - 1)) >= d) ? ps[tid + 1024   - d] : 0.0f;
                float t3 = (((tid + 1536)  & (m - 1)) >= d) ? ps[tid + 1536   - d] : 0.0f;
                __syncthreads();
                ps[tid] += t0; ps[tid + 512] += t1;
                ps[tid + 1024] += t2; ps[tid + 1536] += t3;
                __syncthreads();
            }
            // cross pairs: every R element q vs its value-sorted L sibling block
            for (int x = tid; x < S_DIM; x += NTHR) {
                if (x & m) {
                    int Lb = x & ~(2 * m - 1);
                    float t = cur[x] + 0.5f;
                    int lo = 0, hi = m;
                    while (lo < hi) {
                        int mid = (lo + hi) >> 1;
                        if (cur[Lb + mid] < t) lo = mid + 1; else hi = mid;
                    }
                    if (lo > 0) ord += t * (float)lo - ps[Lb + lo - 1];
                }
            }
            // merge L,R (size m) -> value-sorted 2m blocks (skip at last level)
            if (m < S_DIM / 2) {
                for (int x = tid; x < S_DIM; x += NTHR) {
                    int o  = x & (m - 1);
                    int pb = x & ~(2 * m - 1);
                    bool inL = ((x & m) == 0);
                    int sib = pb + (inL ? m : 0);
                    float v = cur[x];
                    int lo = 0, hi = m;
                    if (inL) {
                        while (lo < hi) { int mid = (lo + hi) >> 1;
                            if (cur[sib + mid] <  v) lo = mid + 1; else hi = mid; }
                    } else {
                        while (lo < hi) { int mid = (lo + hi) >> 1;
                            if (cur[sib + mid] <= v) lo = mid + 1; else hi = mid; }
                    }
                    nxt[pb + o + lo] = v;
                }
                __syncthreads();
                float* tmp = cur; cur = nxt; nxt = tmp;
            }
        }
    } else {
        // ============ BCE STREAM (pure): rows bid-4, step 440 ==============
        const float4* __restrict__ pc4 = reinterpret_cast<const float4*>(pred_causal);
        const int4*   __restrict__ tc4 = reinterpret_cast<const int4*>(target_causal);
        int r = bid - NORD;
        float4 p0 = __ldcs(pc4 + (r << 9) + tid);
        int4   t0 = __ldcs(tc4 + (r << 9) + tid);
        #pragma unroll 1
        for (;;) {
            const int rn = r + NSTRM;
            const bool more = rn < B_DIM * S_DIM;
            float4 p1; int4 t1;
            if (more) {
                p1 = __ldcs(pc4 + (rn << 9) + tid);
                t1 = __ldcs(tc4 + (rn << 9) + tid);
            }
            float v0 = t0.x ? p0.x : (1.0f - p0.x);
            float v1 = t0.y ? p0.y : (1.0f - p0.y);
            float v2 = t0.z ? p0.z : (1.0f - p0.z);
            float v3 = t0.w ? p0.w : (1.0f - p0.w);
            bce -= fmaxf(__logf((v0 * v1) * (v2 * v3)), -100.0f);
            if (!more) break;
            p0 = p1; t0 = t1; r = rn;
        }
    }

    // ============ TRANSITIVITY: all blocks share prec[0] (16 MB) ===========
    {
        const float4* __restrict__ q4 = reinterpret_cast<const float4*>(pred_times);
        const float4 q0 = __ldg(q4 + tid);
        const float4 q1 = __ldg(q4 + 512 + tid);
        const float4 q2 = __ldg(q4 + 1024 + tid);
        const float4 q3 = __ldg(q4 + 1536 + tid);
        const int4* __restrict__ pr4 = reinterpret_cast<const int4*>(target_prec);
        const int j = tid << 2;

        #pragma unroll 1
        for (int i = bid; i < S_DIM; i += NBLK) {
            const int4 pr = __ldcs(pr4 + (i << 9) + tid);
            const float i0 = __ldg(pred_times + i);
            const float i1 = __ldg(pred_times + S_DIM + i);
            const float i2 = __ldg(pred_times + 2 * S_DIM + i);
            const float i3 = __ldg(pred_times + 3 * S_DIM + i);
            int g; float w, s;
            g = j - i;
            w = (g >= 2 && pr.x != 0) ? (float)(g - 1) : 0.0f;
            s = fmaxf(0.1f - (q0.x - i0), 0.0f) + fmaxf(0.1f - (q1.x - i1), 0.0f)
              + fmaxf(0.1f - (q2.x - i2), 0.0f) + fmaxf(0.1f - (q3.x - i3), 0.0f);
            tr += w * s;
            g = j + 1 - i;
            w = (g >= 2 && pr.y != 0) ? (float)(g - 1) : 0.0f;
            s = fmaxf(0.1f - (q0.y - i0), 0.0f) + fmaxf(0.1f - (q1.y - i1), 0.0f)
              + fmaxf(0.1f - (q2.y - i2), 0.0f) + fmaxf(0.1f - (q3.y - i3), 0.0f);
            tr += w * s;
            g = j + 2 - i;
            w = (g >= 2 && pr.z != 0) ? (float)(g - 1) : 0.0f;
            s = fmaxf(0.1f - (q0.z - i0), 0.0f) + fmaxf(0.1f - (q1.z - i1), 0.0f)
              + fmaxf(0.1f - (q2.z - i2), 0.0f) + fmaxf(0.1f - (q3.z - i3), 0.0f);
            tr += w * s;
            g = j + 3 - i;
            w = (g >= 2 && pr.w != 0) ? (float)(g - 1) : 0.0f;
            s = fmaxf(0.1f - (q0.w - i0), 0.0f) + fmaxf(0.1f - (q1.w - i1), 0.0f)
              + fmaxf(0.1f - (q2.w - i2), 0.0f) + fmaxf(0.1f - (q3.w - i3), 0.0f);
            tr += w * s;
        }
    }

    // ---- block reduction in double ----
    sh0[tid] = (double)ord;
    sh1[tid] = (double)bce;
    sh2[tid] = (double)tr;
    __syncthreads();
    #pragma unroll
    for (int off = NTHR / 2; off > 0; off >>= 1) {
        if (tid < off) {
            sh0[tid] += sh0[tid + off];
            sh1[tid] += sh1[tid + off];
            sh2[tid] += sh2[tid + off];
        }
        __syncthreads();
    }

    // ---- write partial + ticket; dynamically-last block finalizes ----
    __shared__ bool s_is_last;
    if (tid == 0) {
        g_part[bid][0] = sh0[0];
        g_part[bid][1] = sh1[0];
        g_part[bid][2] = sh2[0];
        __threadfence();
        unsigned int t = atomicAdd(&g_ticket, 1u);
        s_is_last = (t == (unsigned)(NBLK - 1));
    }
    __syncthreads();

    if (s_is_last) {
        double a0 = 0.0, a1 = 0.0, a2 = 0.0;
        for (int k2 = tid; k2 < NBLK; k2 += NTHR) {
            a0 += g_part[k2][0];
            a1 += g_part[k2][1];
            a2 += g_part[k2][2];
        }
        sh0[tid] = a0; sh1[tid] = a1; sh2[tid] = a2;
        __syncthreads();
        #pragma unroll
        for (int off = NTHR / 2; off > 0; off >>= 1) {
            if (tid < off) {
                sh0[tid] += sh0[tid + off];
                sh1[tid] += sh1[tid + off];
                sh2[tid] += sh2[tid + off];
            }
            __syncthreads();
        }
        if (tid == 0) {
            const double N = (double)NTOT;
            // 0.5 per non-(tt_i<tt_j) ordered pair: 4 batches * 0.5*(S^2 - S(S-1)/2)
            const double ORD_CONST = 2.0 * (double)(SS - (S_DIM * (S_DIM - 1)) / 2);
            double ordering  = (sh0[0] + ORD_CONST) / N;
            double causality = sh1[0] / N;
            const double denom = (double)S_DIM * (S_DIM - 1) * (S_DIM - 2) / 6.0;
            double transitivity = (sh2[0] * 0.25) / denom;   // mean over B=4
            double total = ordering + 0.8 * causality + 0.6 * transitivity;
            if (out_size >= 4) {
                out[0] = (float)ordering;
                out[1] = (float)causality;
                out[2] = (float)transitivity;
                out[3] = (float)total;
            } else {
                out[0] = (float)total;
            }
            __threadfence();
            g_ticket = 0;   // reset for next graph replay
        }
    }
}

extern "C" void kernel_launch(void* const* d_in, const int* in_sizes, int n_in,
                              void* d_out, int out_size) {
    const float* pred_times    = (const float*)d_in[0];
    const float* pred_causal   = (const float*)d_in[1];
    const float* target_times  = (const float*)d_in[2];
    const int*   target_causal = (const int*)d_in[3];
    const int*   target_prec   = (const int*)d_in[4];
    float* out = (float*)d_out;

    tcl_kernel<<<NBLK, NTHR>>>(pred_times, pred_causal, target_times,
                               target_causal, target_prec, out, out_size);
}